// round 5
// baseline (speedup 1.0000x reference)
#include <cuda_runtime.h>
#include <cuda_bf16.h>
#include <stdint.h>

// KAN_6597069767329: per-input-feature cubic B-spline least squares.
//   x [N,64] f32, y [N,64,16] f32, grid uniform (hardcoded)
//   out [16,64,11] f32 : out[o,i,k] = solve(A_i^T A_i, A_i^T B_i)[k,o]

#define IN_F   64
#define OUT_F  16
#define KB     11
#define NCH    37            // 32 pairs * 37 = 1184 = 8 * 148 SMs exactly
#define MCH    8             // moment chunks
#define TILE   256
#define NMAX   100352

typedef unsigned long long ull;

__device__ float g_xT[IN_F * NMAX];
// [feat][chunk][sh(2)][oh(2)][o(8)][k(12)]
__device__ float g_pAtB[IN_F * NCH * 2 * 2 * 8 * 12];
// [feat][mchunk][56]
__device__ float g_pMom[IN_F * MCH * 56];

// ---- smem layout (floats) for accum ----------------------------------------
#define YS_STRIDE 36
#define YS_BUF    (TILE * YS_STRIDE)            // 9216 floats (row = 144B, 16B aligned)
#define BS_OFF    (3 * YS_BUF)                  // 27648
#define BS_STRIDE 14
#define BS_FEAT   (TILE * BS_STRIDE)            // 3584
#define BS_BUF    (2 * BS_FEAT)                 // 7168 (2 features)
#define MBAR_OFF  (BS_OFF + 2 * BS_BUF)         // 41984
#define SMEM_FLOATS (MBAR_OFF + 16)             // + 3 mbarriers (pad)

// ---- helpers ---------------------------------------------------------------
__device__ __forceinline__ void fma2(ull &acc, ull a, ull b) {
    asm("fma.rn.f32x2 %0, %1, %2, %0;" : "+l"(acc) : "l"(a), "l"(b));
}
__device__ __forceinline__ ull bcast2(float v) {
    ull r; unsigned int u = __float_as_uint(v);
    asm("mov.b64 %0, {%1, %1};" : "=l"(r) : "r"(u));
    return r;
}
__device__ __forceinline__ ull wred2(ull v) {
#pragma unroll
    for (int m = 16; m > 0; m >>= 1) {
        ull o = __shfl_xor_sync(0xffffffffu, v, m);
        asm("add.rn.f32x2 %0, %0, %1;" : "+l"(v) : "l"(o));
    }
    return v;
}
__device__ __forceinline__ unsigned smem_u32(const void* p) {
    return (unsigned)__cvta_generic_to_shared(p);
}
__device__ __forceinline__ void mbar_init(unsigned mbar, unsigned count) {
    asm volatile("mbarrier.init.shared.b64 [%0], %1;" :: "r"(mbar), "r"(count) : "memory");
}
__device__ __forceinline__ void mbar_expect_tx(unsigned mbar, unsigned bytes) {
    asm volatile("mbarrier.arrive.expect_tx.shared.b64 _, [%0], %1;"
                 :: "r"(mbar), "r"(bytes) : "memory");
}
__device__ __forceinline__ void mbar_wait(unsigned mbar, unsigned parity) {
    asm volatile(
        "{\n\t.reg .pred P;\n\t"
        "WAITLP_%=:\n\t"
        "mbarrier.try_wait.parity.acquire.cta.shared::cta.b64 P, [%0], %1;\n\t"
        "@!P bra WAITLP_%=;\n\t}"
        :: "r"(mbar), "r"(parity) : "memory");
}
__device__ __forceinline__ void bulk_cp128(unsigned dst, const void* src, unsigned mbar) {
    asm volatile(
        "cp.async.bulk.shared::cta.global.mbarrier::complete_tx::bytes [%0], [%1], 128, [%2];"
        :: "r"(dst), "l"(src), "r"(mbar) : "memory");
}

// ---- phase 0: transpose x [N,64] -> xT [64,N] ------------------------------
__global__ void transpose_kernel(const float* __restrict__ x, int N) {
    __shared__ float tile[32][33];
    int n0 = blockIdx.x * 32;
    int c0 = blockIdx.y * 32;
#pragma unroll
    for (int r = 0; r < 4; r++) {
        int row = threadIdx.y + r * 8;
        int n = n0 + row;
        if (n < N) tile[row][threadIdx.x] = x[(size_t)n * IN_F + c0 + threadIdx.x];
    }
    __syncthreads();
#pragma unroll
    for (int r = 0; r < 4; r++) {
        int f = threadIdx.y + r * 8;
        int n = n0 + threadIdx.x;
        if (n < N) g_xT[(size_t)(c0 + f) * N + n] = tile[threadIdx.x][f];
    }
}

// ---- phase 0b: per-cell u-power moments (for AtA reconstruction) ----------
__global__ __launch_bounds__(256) void moments_kernel(int N) {
    const int chunk = blockIdx.x;
    const int feat  = blockIdx.y;
    const int t = threadIdx.x;
    const int warp = t >> 5, lane = t & 31;

    const int per  = (N + MCH - 1) / MCH;
    const int s_lo = chunk * per;
    const int s_hi = min(N, s_lo + per);

    float mom[8][7];
#pragma unroll
    for (int jc = 0; jc < 8; jc++)
#pragma unroll
        for (int p = 0; p < 7; p++) mom[jc][p] = 0.f;

    const float* xT = g_xT + (size_t)feat * N;
    for (int s = s_lo + t; s < s_hi; s += 256) {
        float xv = __ldg(xT + s);
        float tt = (xv + 1.0f) * 4.0f;
        int j = (int)floorf(tt);
        j = max(0, min(7, j));
        float u = tt - (float)j;
        float up[7];
        up[0] = 1.f;
#pragma unroll
        for (int p = 1; p < 7; p++) up[p] = up[p - 1] * u;
#pragma unroll
        for (int jc = 0; jc < 8; jc++) {
            float sel = (jc == j) ? 1.f : 0.f;
#pragma unroll
            for (int p = 0; p < 7; p++) mom[jc][p] += sel * up[p];
        }
    }

    __shared__ float red[8 * 57];
#pragma unroll
    for (int jc = 0; jc < 8; jc++)
#pragma unroll
        for (int p = 0; p < 7; p++) {
            float v = mom[jc][p];
#pragma unroll
            for (int m = 16; m > 0; m >>= 1)
                v += __shfl_xor_sync(0xffffffffu, v, m);
            if (lane == 0) red[warp * 57 + jc * 7 + p] = v;
        }
    __syncthreads();
    if (t < 56) {
        float s = 0.f;
#pragma unroll
        for (int w = 0; w < 8; w++) s += red[w * 57 + t];
        g_pMom[((size_t)feat * MCH + chunk) * 56 + t] = s;
    }
}

// ---- phase 1: AtB accumulation (feature pairs, bulk-copy y staging) --------
__global__ __launch_bounds__(256, 1) void accum_kernel(const float* __restrict__ y, int N) {
    extern __shared__ float sm[];
    float* Ys = sm;                 // 3 bufs [256][36]: [sample][feat*16 + o]
    float* Bs = sm + BS_OFF;        // 2 bufs [2 feat][256][14]
    unsigned mbar0 = smem_u32(sm + MBAR_OFF);   // 3 mbarriers, 8B apart

    const int pair  = blockIdx.y;
    const int chunk = blockIdx.x;
    const int i0 = pair * 2;
    const int t = threadIdx.x;
    const int warp = t >> 5, lane = t & 31;
    const int fw = warp & 1;
    const int oh = (warp >> 1) & 1;
    const int sh = warp >> 2;

    const int per  = (N + NCH - 1) / NCH;
    const int s_lo = chunk * per;
    const int s_hi = min(N, s_lo + per);
    const int nt   = (s_hi - s_lo + TILE - 1) / TILE;

    const float* xT0 = g_xT + (size_t)i0 * N;
    const float* xT1 = g_xT + (size_t)(i0 + 1) * N;

    ull acc[48];
#pragma unroll
    for (int q = 0; q < 48; q++) acc[q] = 0ull;

    if (t == 0) {
        mbar_init(mbar0,      1);
        mbar_init(mbar0 + 8,  1);
        mbar_init(mbar0 + 16, 1);
    }
    __syncthreads();

    auto stage_basis = [&](int ti, int bb) {
        float* row0 = Bs + bb * BS_BUF + t * BS_STRIDE;
        float* row1 = row0 + BS_FEAT;
        float2 z2 = make_float2(0.f, 0.f);
#pragma unroll
        for (int q = 0; q < 6; q++) { ((float2*)row0)[q] = z2; ((float2*)row1)[q] = z2; }
        int s = s_lo + ti * TILE + t;
        if (s < s_hi) {
            float xv0 = __ldg(xT0 + s);
            float xv1 = __ldg(xT1 + s);
#pragma unroll
            for (int f = 0; f < 2; f++) {
                float xv = f ? xv1 : xv0;
                float* row = f ? row1 : row0;
                float tt = (xv + 1.0f) * 4.0f;
                int j = (int)floorf(tt);
                j = max(0, min(7, j));
                float u = tt - (float)j;
                float um = 1.0f - u;
                float u2 = u * u, u3 = u2 * u;
                float um3 = um * um * um;
                const float c6 = 1.0f / 6.0f;
                row[j]     = um3 * c6;
                row[j + 1] = (3.0f * u3 - 6.0f * u2 + 4.0f) * c6;
                row[j + 2] = (-3.0f * u3 + 3.0f * u2 + 3.0f * u + 1.0f) * c6;
                row[j + 3] = u3 * c6;
            }
        }
    };

    // one 128B bulk copy per thread per tile; thread 0 sets expect_tx
    auto issue_y = [&](int ti) {
        int b3 = ti % 3;
        unsigned mb = mbar0 + 8u * b3;
        int s0 = s_lo + ti * TILE;
        int valid = min(TILE, s_hi - s0);          // >=1 when called
        if (t == 0) mbar_expect_tx(mb, (unsigned)valid * 128u);
        float* dstp = Ys + b3 * YS_BUF + t * YS_STRIDE;
        int s = s0 + t;
        if (t < valid) {
            bulk_cp128(smem_u32(dstp), y + ((size_t)s * IN_F + i0) * OUT_F, mb);
        } else {
            float4 z = make_float4(0.f, 0.f, 0.f, 0.f);
#pragma unroll
            for (int q = 0; q < 8; q++) ((float4*)dstp)[q] = z;
        }
    };

    // prolog
    stage_basis(0, 0);
    issue_y(0);
    if (nt > 1) issue_y(1);

    for (int i = 0; i < nt; i++) {
        const int b3 = i % 3, b2 = i & 1;
        mbar_wait(mbar0 + 8u * b3, (unsigned)((i / 3) & 1));
        __syncthreads();                      // basis buf + zero-fills + buffer reuse
        if (i + 2 < nt) issue_y(i + 2);

        const float* BsC = Bs + b2 * BS_BUF + fw * BS_FEAT;
        const float* YsC = Ys + b3 * YS_BUF;
#pragma unroll
        for (int jj = 0; jj < 4; jj++) {
            int sl = sh * 128 + jj * 32 + lane;
            const float* brow = BsC + sl * BS_STRIDE;
            const float4* yrow = (const float4*)(YsC + sl * YS_STRIDE + fw * 16 + oh * 8);
            float4 ya = yrow[0];
            float4 yb = yrow[1];
            ull b2v[6];
#pragma unroll
            for (int kp = 0; kp < 6; kp++)
                b2v[kp] = *(const ull*)(brow + 2 * kp);
            ull yB[8];
            yB[0] = bcast2(ya.x); yB[1] = bcast2(ya.y);
            yB[2] = bcast2(ya.z); yB[3] = bcast2(ya.w);
            yB[4] = bcast2(yb.x); yB[5] = bcast2(yb.y);
            yB[6] = bcast2(yb.z); yB[7] = bcast2(yb.w);
#pragma unroll
            for (int kp = 0; kp < 6; kp++)
#pragma unroll
                for (int o = 0; o < 8; o++)
                    fma2(acc[kp * 8 + o], b2v[kp], yB[o]);
        }

        if (i + 1 < nt) stage_basis(i + 1, (i + 1) & 1);
    }

#pragma unroll
    for (int q = 0; q < 48; q++) acc[q] = wred2(acc[q]);
    if (lane == 0) {
        size_t base = ((((size_t)(i0 + fw) * NCH + chunk) * 2 + sh) * 2 + oh) * 96;
#pragma unroll
        for (int o = 0; o < 8; o++)
#pragma unroll
            for (int kp = 0; kp < 6; kp++)
                *(ull*)(g_pAtB + base + o * 12 + 2 * kp) = acc[kp * 8 + o];
    }
}

// triangle index (a <= b)
__device__ __forceinline__ int tidx(int a, int b) {
    return a * KB - (a * (a - 1)) / 2 + (b - a);
}

__device__ __constant__ double CAD[4][4] = {
    {1.0, -3.0,  3.0, -1.0},
    {4.0,  0.0, -6.0,  3.0},
    {1.0,  3.0,  3.0, -3.0},
    {0.0,  0.0,  0.0,  1.0}
};

// ---- phase 2: AtA from moments (double build), FLOAT Cholesky solve --------
__global__ void solve_kernel(float* __restrict__ out) {
    const int i = blockIdx.x;
    const int t = threadIdx.x;      // 128
    __shared__ float  sAtB[12][OUT_F];
    __shared__ double sS[56];
    __shared__ double sAtAd[66];
    __shared__ float  sL[66];
    __shared__ float  sLinv[KB];

    for (int e = t; e < 12 * OUT_F; e += 128) {
        int k = e % 12, o = e / 12;
        int ohh = o >> 3, oo = o & 7;
        float s = 0.f;
        for (int c = 0; c < NCH; c++)
            for (int q = 0; q < 2; q++)
                s += g_pAtB[(((((size_t)i * NCH + c) * 2 + q) * 2 + ohh) * 8 + oo) * 12 + k];
        sAtB[k][o] = s;
    }
    for (int p = t; p < 56; p += 128) {
        double s = 0.0;
        for (int c = 0; c < MCH; c++)
            s += (double)g_pMom[((size_t)i * MCH + c) * 56 + p];
        sS[p] = s;
    }
    __syncthreads();

    if (t < 66) {
        int p = t, r = 0;
        while (p >= KB - r) { p -= KB - r; r++; }
        int cc = r + p;
        double val = 0.0;
        for (int j = 0; j < 8; j++) {
            int a = r - j, b = cc - j;
            if (a >= 0 && a < 4 && b >= 0 && b < 4) {
                for (int p1 = 0; p1 < 4; p1++)
                    for (int q1 = 0; q1 < 4; q1++)
                        val += CAD[a][p1] * CAD[b][q1] * sS[j * 7 + p1 + q1];
            }
        }
        sAtAd[t] = val / 36.0;
    }
    __syncthreads();

    if (t == 0) {
        // float Cholesky (upper-tri storage), reciprocal diagonals
        for (int j = 0; j < KB; j++) {
            float d = (float)sAtAd[tidx(j, j)];
            for (int m = 0; m < j; m++) { float v = sL[tidx(m, j)]; d -= v * v; }
            d = sqrtf(d);
            sL[tidx(j, j)] = d;
            float inv = 1.0f / d;
            sLinv[j] = inv;
            for (int r = j + 1; r < KB; r++) {
                float s = (float)sAtAd[tidx(j, r)];
                for (int m = 0; m < j; m++) s -= sL[tidx(m, r)] * sL[tidx(m, j)];
                sL[tidx(j, r)] = s * inv;
            }
        }
    }
    __syncthreads();

    if (t < OUT_F) {
        const int o = t;
        float z[KB], X[KB];
        for (int r = 0; r < KB; r++) {
            float s = sAtB[r][o];
            for (int m = 0; m < r; m++) s -= sL[tidx(m, r)] * z[m];
            z[r] = s * sLinv[r];
        }
        for (int r = KB - 1; r >= 0; r--) {
            float s = z[r];
            for (int m = r + 1; m < KB; m++) s -= sL[tidx(r, m)] * X[m];
            X[r] = s * sLinv[r];
            out[(size_t)o * (IN_F * KB) + i * KB + r] = X[r];
        }
    }
}

extern "C" void kernel_launch(void* const* d_in, const int* in_sizes, int n_in,
                              void* d_out, int out_size) {
    const float* x = (const float*)d_in[0];
    const float* y = (const float*)d_in[1];
    (void)n_in; (void)out_size;
    float* out = (float*)d_out;
    int N = in_sizes[0] / IN_F;

    cudaFuncSetAttribute(accum_kernel,
                         cudaFuncAttributeMaxDynamicSharedMemorySize,
                         SMEM_FLOATS * (int)sizeof(float));

    dim3 tgrid((N + 31) / 32, IN_F / 32);
    transpose_kernel<<<tgrid, dim3(32, 8)>>>(x, N);

    moments_kernel<<<dim3(MCH, IN_F), 256>>>(N);

    accum_kernel<<<dim3(NCH, 32), 256, SMEM_FLOATS * (int)sizeof(float)>>>(y, N);

    solve_kernel<<<IN_F, 128>>>(out);
}

// round 6
// speedup vs baseline: 1.2061x; 1.2061x over previous
#include <cuda_runtime.h>
#include <cuda_bf16.h>
#include <stdint.h>

// KAN_6597069767329: per-input-feature cubic B-spline least squares.
//   x [N,64] f32, y [N,64,16] f32, grid uniform (hardcoded)
//   out [16,64,11] f32 : out[o,i,k] = solve(A_i^T A_i, A_i^T B_i)[k,o]

#define IN_F   64
#define OUT_F  16
#define KB     11
#define NCH    37            // 32 pairs * 37 = 1184 = 8 * 148 SMs exactly
#define MCH    8             // moment chunks
#define TILE   256
#define NMAX   100352

typedef unsigned long long ull;

__device__ float g_xT[IN_F * NMAX];
// [feat][chunk][sh(2)][oh(2)][o(8)][k(12)]
__device__ float g_pAtB[IN_F * NCH * 2 * 2 * 8 * 12];
// [feat][mchunk][56]
__device__ float g_pMom[IN_F * MCH * 56];

// ---- smem layout (floats) for accum ----------------------------------------
#define YS_STRIDE 36
#define YS_BUF    (TILE * YS_STRIDE)            // 9216 floats / buf (36 KB)
#define YS_NBUF   4
#define BS_OFF    (YS_NBUF * YS_BUF)            // 36864
#define BS_STRIDE 14
#define BS_FEAT   (TILE * BS_STRIDE)            // 3584
#define BS_BUF    (2 * BS_FEAT)                 // 7168 (2 features)
#define SMEM_FLOATS (BS_OFF + 2 * BS_BUF)       // 51200 floats = 204800 B

// ---- helpers ---------------------------------------------------------------
__device__ __forceinline__ void fma2(ull &acc, ull a, ull b) {
    asm("fma.rn.f32x2 %0, %1, %2, %0;" : "+l"(acc) : "l"(a), "l"(b));
}
__device__ __forceinline__ ull bcast2(float v) {
    ull r; unsigned int u = __float_as_uint(v);
    asm("mov.b64 %0, {%1, %1};" : "=l"(r) : "r"(u));
    return r;
}
__device__ __forceinline__ ull wred2(ull v) {
#pragma unroll
    for (int m = 16; m > 0; m >>= 1) {
        ull o = __shfl_xor_sync(0xffffffffu, v, m);
        asm("add.rn.f32x2 %0, %0, %1;" : "+l"(v) : "l"(o));
    }
    return v;
}
__device__ __forceinline__ unsigned smem_u32(const void* p) {
    return (unsigned)__cvta_generic_to_shared(p);
}
__device__ __forceinline__ void cp16(unsigned dst, const void* src) {
    asm volatile("cp.async.cg.shared.global [%0], [%1], 16;" :: "r"(dst), "l"(src));
}
__device__ __forceinline__ void cp_commit() {
    asm volatile("cp.async.commit_group;");
}
__device__ __forceinline__ void cp_wait2() {
    asm volatile("cp.async.wait_group 2;");
}

// ---- phase 0: transpose x [N,64] -> xT [64,N] ------------------------------
__global__ void transpose_kernel(const float* __restrict__ x, int N) {
    __shared__ float tile[32][33];
    int n0 = blockIdx.x * 32;
    int c0 = blockIdx.y * 32;
#pragma unroll
    for (int r = 0; r < 4; r++) {
        int row = threadIdx.y + r * 8;
        int n = n0 + row;
        if (n < N) tile[row][threadIdx.x] = x[(size_t)n * IN_F + c0 + threadIdx.x];
    }
    __syncthreads();
#pragma unroll
    for (int r = 0; r < 4; r++) {
        int f = threadIdx.y + r * 8;
        int n = n0 + threadIdx.x;
        if (n < N) g_xT[(size_t)(c0 + f) * N + n] = tile[threadIdx.x][f];
    }
}

// ---- phase 0b: per-cell u-power moments (for AtA reconstruction) ----------
__global__ __launch_bounds__(256) void moments_kernel(int N) {
    const int chunk = blockIdx.x;
    const int feat  = blockIdx.y;
    const int t = threadIdx.x;
    const int warp = t >> 5, lane = t & 31;

    const int per  = (N + MCH - 1) / MCH;
    const int s_lo = chunk * per;
    const int s_hi = min(N, s_lo + per);

    float mom[8][7];
#pragma unroll
    for (int jc = 0; jc < 8; jc++)
#pragma unroll
        for (int p = 0; p < 7; p++) mom[jc][p] = 0.f;

    const float* xT = g_xT + (size_t)feat * N;
    for (int s = s_lo + t; s < s_hi; s += 256) {
        float xv = __ldg(xT + s);
        float tt = (xv + 1.0f) * 4.0f;
        int j = (int)floorf(tt);
        j = max(0, min(7, j));
        float u = tt - (float)j;
        float up[7];
        up[0] = 1.f;
#pragma unroll
        for (int p = 1; p < 7; p++) up[p] = up[p - 1] * u;
#pragma unroll
        for (int jc = 0; jc < 8; jc++) {
            float sel = (jc == j) ? 1.f : 0.f;
#pragma unroll
            for (int p = 0; p < 7; p++) mom[jc][p] += sel * up[p];
        }
    }

    __shared__ float red[8 * 57];
#pragma unroll
    for (int jc = 0; jc < 8; jc++)
#pragma unroll
        for (int p = 0; p < 7; p++) {
            float v = mom[jc][p];
#pragma unroll
            for (int m = 16; m > 0; m >>= 1)
                v += __shfl_xor_sync(0xffffffffu, v, m);
            if (lane == 0) red[warp * 57 + jc * 7 + p] = v;
        }
    __syncthreads();
    if (t < 56) {
        float s = 0.f;
#pragma unroll
        for (int w = 0; w < 8; w++) s += red[w * 57 + t];
        g_pMom[((size_t)feat * MCH + chunk) * 56 + t] = s;
    }
}

// ---- phase 1: AtB accumulation (feature pairs, deep LDGSTS pipeline) -------
__global__ __launch_bounds__(256, 1) void accum_kernel(const float* __restrict__ y, int N) {
    extern __shared__ float sm[];
    float* Ys = sm;                 // 4 bufs [256][36]: [sample][feat*16 + o]
    float* Bs = sm + BS_OFF;        // 2 bufs [2 feat][256][14]

    const int pair  = blockIdx.y;
    const int chunk = blockIdx.x;
    const int i0 = pair * 2;
    const int t = threadIdx.x;
    const int warp = t >> 5, lane = t & 31;
    const int fw = warp & 1;
    const int oh = (warp >> 1) & 1;
    const int sh = warp >> 2;

    const int per  = (N + NCH - 1) / NCH;
    const int s_lo = chunk * per;
    const int s_hi = min(N, s_lo + per);
    const int nt   = (s_hi - s_lo + TILE - 1) / TILE;

    const float* xT0 = g_xT + (size_t)i0 * N;
    const float* xT1 = g_xT + (size_t)(i0 + 1) * N;

    ull acc[48];
#pragma unroll
    for (int q = 0; q < 48; q++) acc[q] = 0ull;

    auto stage_basis = [&](int ti, int bb) {
        float* row0 = Bs + bb * BS_BUF + t * BS_STRIDE;
        float* row1 = row0 + BS_FEAT;
        float2 z2 = make_float2(0.f, 0.f);
#pragma unroll
        for (int q = 0; q < 6; q++) { ((float2*)row0)[q] = z2; ((float2*)row1)[q] = z2; }
        int s = s_lo + ti * TILE + t;
        if (s < s_hi) {
            float xv0 = __ldg(xT0 + s);
            float xv1 = __ldg(xT1 + s);
#pragma unroll
            for (int f = 0; f < 2; f++) {
                float xv = f ? xv1 : xv0;
                float* row = f ? row1 : row0;
                float tt = (xv + 1.0f) * 4.0f;
                int j = (int)floorf(tt);
                j = max(0, min(7, j));
                float u = tt - (float)j;
                float um = 1.0f - u;
                float u2 = u * u, u3 = u2 * u;
                float um3 = um * um * um;
                const float c6 = 1.0f / 6.0f;
                row[j]     = um3 * c6;
                row[j + 1] = (3.0f * u3 - 6.0f * u2 + 4.0f) * c6;
                row[j + 2] = (-3.0f * u3 + 3.0f * u2 + 3.0f * u + 1.0f) * c6;
                row[j + 3] = u3 * c6;
            }
        }
    };
    auto issue_y = [&](int ti) {
        int b = ti % YS_NBUF;
        int s0 = s_lo + ti * TILE;
#pragma unroll
        for (int e = t; e < TILE * 8; e += 256) {
            int sloc = e >> 3, q = e & 7;
            int s = s0 + sloc;
            float* dstp = Ys + b * YS_BUF + sloc * YS_STRIDE + q * 4;
            if (s < s_hi)
                cp16(smem_u32(dstp), y + ((size_t)s * IN_F + i0) * OUT_F + q * 4);
            else
                *(float4*)dstp = make_float4(0.f, 0.f, 0.f, 0.f);
        }
    };

    // prolog: stage basis 0; issue y tiles 0..2 (3 groups committed)
    stage_basis(0, 0);
    issue_y(0); cp_commit();
    if (nt > 1) issue_y(1);
    cp_commit();
    if (nt > 2) issue_y(2);
    cp_commit();

    for (int i = 0; i < nt; i++) {
        const int b = i % YS_NBUF, b2 = i & 1;
        cp_wait2();                 // groups committed so far = 3+i; done >= i+1
        __syncthreads();
        if (i + 3 < nt) issue_y(i + 3);
        cp_commit();                // unconditional: keeps group count = 1/iter

        const float* BsC = Bs + b2 * BS_BUF + fw * BS_FEAT;
        const float* YsC = Ys + b * YS_BUF;
#pragma unroll
        for (int jj = 0; jj < 4; jj++) {
            int sl = sh * 128 + jj * 32 + lane;
            const float* brow = BsC + sl * BS_STRIDE;
            const float4* yrow = (const float4*)(YsC + sl * YS_STRIDE + fw * 16 + oh * 8);
            float4 ya = yrow[0];
            float4 yb = yrow[1];
            ull b2v[6];
#pragma unroll
            for (int kp = 0; kp < 6; kp++)
                b2v[kp] = *(const ull*)(brow + 2 * kp);
            ull yB[8];
            yB[0] = bcast2(ya.x); yB[1] = bcast2(ya.y);
            yB[2] = bcast2(ya.z); yB[3] = bcast2(ya.w);
            yB[4] = bcast2(yb.x); yB[5] = bcast2(yb.y);
            yB[6] = bcast2(yb.z); yB[7] = bcast2(yb.w);
#pragma unroll
            for (int kp = 0; kp < 6; kp++)
#pragma unroll
                for (int o = 0; o < 8; o++)
                    fma2(acc[kp * 8 + o], b2v[kp], yB[o]);
        }

        if (i + 1 < nt) stage_basis(i + 1, (i + 1) & 1);
    }

#pragma unroll
    for (int q = 0; q < 48; q++) acc[q] = wred2(acc[q]);
    if (lane == 0) {
        size_t base = ((((size_t)(i0 + fw) * NCH + chunk) * 2 + sh) * 2 + oh) * 96;
#pragma unroll
        for (int o = 0; o < 8; o++)
#pragma unroll
            for (int kp = 0; kp < 6; kp++)
                *(ull*)(g_pAtB + base + o * 12 + 2 * kp) = acc[kp * 8 + o];
    }
}

// triangle index (a <= b)
__device__ __forceinline__ int tidx(int a, int b) {
    return a * KB - (a * (a - 1)) / 2 + (b - a);
}

__device__ __constant__ double CAD[4][4] = {
    {1.0, -3.0,  3.0, -1.0},
    {4.0,  0.0, -6.0,  3.0},
    {1.0,  3.0,  3.0, -3.0},
    {0.0,  0.0,  0.0,  1.0}
};

// ---- phase 2: parallel partial reduction + float Cholesky solve ------------
__global__ __launch_bounds__(256) void solve_kernel(float* __restrict__ out) {
    const int i = blockIdx.x;
    const int t = threadIdx.x;      // 256
    __shared__ float  sAtB[12][OUT_F];
    __shared__ double sS[56];
    __shared__ double sAtAd[66];
    __shared__ float  sL[66];
    __shared__ float  sLinv[KB];

    if (t < 192) {
        // one (k,o) entry per thread; 74 independent strided loads, MLP-unrolled
        int k = t % 12, o = t / 12;
        int ohh = o >> 3, oo = o & 7;
        const float* p = g_pAtB + (size_t)i * (NCH * 2 * 2 * 96)
                       + ohh * 96 + oo * 12 + k;
        float s = 0.f;
#pragma unroll 8
        for (int cs = 0; cs < NCH * 2; cs++)
            s += p[(size_t)cs * 192];
        sAtB[k][o] = s;
    } else if (t < 248) {
        int p = t - 192;            // 0..55
        const float* q = g_pMom + (size_t)i * (MCH * 56) + p;
        double s = 0.0;
#pragma unroll
        for (int c = 0; c < MCH; c++)
            s += (double)q[c * 56];
        sS[p] = s;
    }
    __syncthreads();

    if (t < 66) {
        int p = t, r = 0;
        while (p >= KB - r) { p -= KB - r; r++; }
        int cc = r + p;
        double val = 0.0;
        for (int j = 0; j < 8; j++) {
            int a = r - j, b = cc - j;
            if (a >= 0 && a < 4 && b >= 0 && b < 4) {
                for (int p1 = 0; p1 < 4; p1++)
                    for (int q1 = 0; q1 < 4; q1++)
                        val += CAD[a][p1] * CAD[b][q1] * sS[j * 7 + p1 + q1];
            }
        }
        sAtAd[t] = val / 36.0;
    }
    __syncthreads();

    if (t == 0) {
        for (int j = 0; j < KB; j++) {
            float d = (float)sAtAd[tidx(j, j)];
            for (int m = 0; m < j; m++) { float v = sL[tidx(m, j)]; d -= v * v; }
            d = sqrtf(d);
            sL[tidx(j, j)] = d;
            float inv = 1.0f / d;
            sLinv[j] = inv;
            for (int r = j + 1; r < KB; r++) {
                float s = (float)sAtAd[tidx(j, r)];
                for (int m = 0; m < j; m++) s -= sL[tidx(m, r)] * sL[tidx(m, j)];
                sL[tidx(j, r)] = s * inv;
            }
        }
    }
    __syncthreads();

    if (t < OUT_F) {
        const int o = t;
        float z[KB], X[KB];
        for (int r = 0; r < KB; r++) {
            float s = sAtB[r][o];
            for (int m = 0; m < r; m++) s -= sL[tidx(m, r)] * z[m];
            z[r] = s * sLinv[r];
        }
        for (int r = KB - 1; r >= 0; r--) {
            float s = z[r];
            for (int m = r + 1; m < KB; m++) s -= sL[tidx(r, m)] * X[m];
            X[r] = s * sLinv[r];
            out[(size_t)o * (IN_F * KB) + i * KB + r] = X[r];
        }
    }
}

extern "C" void kernel_launch(void* const* d_in, const int* in_sizes, int n_in,
                              void* d_out, int out_size) {
    const float* x = (const float*)d_in[0];
    const float* y = (const float*)d_in[1];
    (void)n_in; (void)out_size;
    float* out = (float*)d_out;
    int N = in_sizes[0] / IN_F;

    cudaFuncSetAttribute(accum_kernel,
                         cudaFuncAttributeMaxDynamicSharedMemorySize,
                         SMEM_FLOATS * (int)sizeof(float));

    dim3 tgrid((N + 31) / 32, IN_F / 32);
    transpose_kernel<<<tgrid, dim3(32, 8)>>>(x, N);

    moments_kernel<<<dim3(MCH, IN_F), 256>>>(N);

    accum_kernel<<<dim3(NCH, 32), 256, SMEM_FLOATS * (int)sizeof(float)>>>(y, N);

    solve_kernel<<<IN_F, 256>>>(out);
}

// round 7
// speedup vs baseline: 1.4668x; 1.2162x over previous
#include <cuda_runtime.h>
#include <cuda_bf16.h>
#include <stdint.h>

// KAN_6597069767329: per-input-feature cubic B-spline least squares.
//   x [N,64] f32, y [N,64,16] f32, grid uniform (hardcoded)
//   out [16,64,11] f32 : out[o,i,k] = solve(A_i^T A_i, A_i^T B_i)[k,o]

#define IN_F   64
#define OUT_F  16
#define KB     11
#define NCH    37            // 32 pairs * 37 = 1184 = 8 * 148 SMs exactly
#define MCH    8             // moment chunks
#define TILE   256
#define NMAX   100352

typedef unsigned long long ull;

__device__ float g_xT[IN_F * NMAX];
// [feat][chunk][sh(2)][oh(2)][o(8)][k(12)]
__device__ float g_pAtB[IN_F * NCH * 2 * 2 * 8 * 12];
// [feat][mchunk][56]
__device__ float g_pMom[IN_F * MCH * 56];

// ---- smem layout (floats) for accum ----------------------------------------
#define YS_STRIDE 36
#define YS_BUF    (TILE * YS_STRIDE)            // 9216 floats / buf (36 KB)
#define YS_NBUF   4
#define BS_OFF    (YS_NBUF * YS_BUF)            // 36864
#define BS_STRIDE 14
#define BS_FEAT   (TILE * BS_STRIDE)            // 3584
#define BS_BUF    (2 * BS_FEAT)                 // 7168 (2 features)
#define SMEM_FLOATS (BS_OFF + 2 * BS_BUF)       // 51200 floats = 204800 B

// ---- helpers ---------------------------------------------------------------
__device__ __forceinline__ void fma2(ull &acc, ull a, ull b) {
    asm("fma.rn.f32x2 %0, %1, %2, %0;" : "+l"(acc) : "l"(a), "l"(b));
}
__device__ __forceinline__ ull bcast2(float v) {
    ull r; unsigned int u = __float_as_uint(v);
    asm("mov.b64 %0, {%1, %1};" : "=l"(r) : "r"(u));
    return r;
}
__device__ __forceinline__ ull wred2(ull v) {
#pragma unroll
    for (int m = 16; m > 0; m >>= 1) {
        ull o = __shfl_xor_sync(0xffffffffu, v, m);
        asm("add.rn.f32x2 %0, %0, %1;" : "+l"(v) : "l"(o));
    }
    return v;
}
__device__ __forceinline__ unsigned smem_u32(const void* p) {
    return (unsigned)__cvta_generic_to_shared(p);
}
__device__ __forceinline__ void cp16(unsigned dst, const void* src) {
    asm volatile("cp.async.cg.shared.global [%0], [%1], 16;" :: "r"(dst), "l"(src));
}
__device__ __forceinline__ void cp_commit() {
    asm volatile("cp.async.commit_group;");
}
__device__ __forceinline__ void cp_wait2() {
    asm volatile("cp.async.wait_group 2;");
}

// ---- phase 0: transpose x [N,64] -> xT [64,N] ------------------------------
__global__ void transpose_kernel(const float* __restrict__ x, int N) {
    __shared__ float tile[32][33];
    int n0 = blockIdx.x * 32;
    int c0 = blockIdx.y * 32;
#pragma unroll
    for (int r = 0; r < 4; r++) {
        int row = threadIdx.y + r * 8;
        int n = n0 + row;
        if (n < N) tile[row][threadIdx.x] = x[(size_t)n * IN_F + c0 + threadIdx.x];
    }
    __syncthreads();
#pragma unroll
    for (int r = 0; r < 4; r++) {
        int f = threadIdx.y + r * 8;
        int n = n0 + threadIdx.x;
        if (n < N) g_xT[(size_t)(c0 + f) * N + n] = tile[threadIdx.x][f];
    }
}

// ---- phase 0b: per-cell u-power moments (for AtA reconstruction) ----------
__global__ __launch_bounds__(256) void moments_kernel(int N) {
    const int chunk = blockIdx.x;
    const int feat  = blockIdx.y;
    const int t = threadIdx.x;
    const int warp = t >> 5, lane = t & 31;

    const int per  = (N + MCH - 1) / MCH;
    const int s_lo = chunk * per;
    const int s_hi = min(N, s_lo + per);

    float mom[8][7];
#pragma unroll
    for (int jc = 0; jc < 8; jc++)
#pragma unroll
        for (int p = 0; p < 7; p++) mom[jc][p] = 0.f;

    const float* xT = g_xT + (size_t)feat * N;
    for (int s = s_lo + t; s < s_hi; s += 256) {
        float xv = __ldg(xT + s);
        float tt = (xv + 1.0f) * 4.0f;
        int j = (int)floorf(tt);
        j = max(0, min(7, j));
        float u = tt - (float)j;
        float up[7];
        up[0] = 1.f;
#pragma unroll
        for (int p = 1; p < 7; p++) up[p] = up[p - 1] * u;
#pragma unroll
        for (int jc = 0; jc < 8; jc++) {
            float sel = (jc == j) ? 1.f : 0.f;
#pragma unroll
            for (int p = 0; p < 7; p++) mom[jc][p] += sel * up[p];
        }
    }

    __shared__ float red[8 * 57];
#pragma unroll
    for (int jc = 0; jc < 8; jc++)
#pragma unroll
        for (int p = 0; p < 7; p++) {
            float v = mom[jc][p];
#pragma unroll
            for (int m = 16; m > 0; m >>= 1)
                v += __shfl_xor_sync(0xffffffffu, v, m);
            if (lane == 0) red[warp * 57 + jc * 7 + p] = v;
        }
    __syncthreads();
    if (t < 56) {
        float s = 0.f;
#pragma unroll
        for (int w = 0; w < 8; w++) s += red[w * 57 + t];
        g_pMom[((size_t)feat * MCH + chunk) * 56 + t] = s;
    }
}

// ---- phase 1: AtB accumulation (prefetched basis, deep LDGSTS pipeline) ----
__global__ __launch_bounds__(256, 1) void accum_kernel(const float* __restrict__ y, int N) {
    extern __shared__ float sm[];
    float* Ys = sm;                 // 4 bufs [256][36]
    float* Bs = sm + BS_OFF;        // 2 bufs [2 feat][256][14]

    const int pair  = blockIdx.y;
    const int chunk = blockIdx.x;
    const int i0 = pair * 2;
    const int t = threadIdx.x;
    const int warp = t >> 5, lane = t & 31;
    const int fw = warp & 1;
    const int oh = (warp >> 1) & 1;
    const int sh = warp >> 2;

    const int per  = (N + NCH - 1) / NCH;
    const int s_lo = chunk * per;
    const int s_hi = min(N, s_lo + per);
    const int nt   = (s_hi - s_lo + TILE - 1) / TILE;

    const float* xT0 = g_xT + (size_t)i0 * N;
    const float* xT1 = g_xT + (size_t)(i0 + 1) * N;

    ull acc[48];
#pragma unroll
    for (int q = 0; q < 48; q++) acc[q] = 0ull;

    // stage basis from registers (no global latency in critical path)
    auto stage_basis_reg = [&](int bb, float xv0, float xv1, bool valid) {
        float* row0 = Bs + bb * BS_BUF + t * BS_STRIDE;
        float* row1 = row0 + BS_FEAT;
        float2 z2 = make_float2(0.f, 0.f);
#pragma unroll
        for (int q = 0; q < 6; q++) { ((float2*)row0)[q] = z2; ((float2*)row1)[q] = z2; }
        if (valid) {
#pragma unroll
            for (int f = 0; f < 2; f++) {
                float xv = f ? xv1 : xv0;
                float* row = f ? row1 : row0;
                float tt = (xv + 1.0f) * 4.0f;
                int j = (int)floorf(tt);
                j = max(0, min(7, j));
                float u = tt - (float)j;
                float um = 1.0f - u;
                float u2 = u * u, u3 = u2 * u;
                float um3 = um * um * um;
                const float c6 = 1.0f / 6.0f;
                row[j]     = um3 * c6;
                row[j + 1] = (3.0f * u3 - 6.0f * u2 + 4.0f) * c6;
                row[j + 2] = (-3.0f * u3 + 3.0f * u2 + 3.0f * u + 1.0f) * c6;
                row[j + 3] = u3 * c6;
            }
        }
    };
    auto issue_y = [&](int ti) {
        int b = ti % YS_NBUF;
        int s0 = s_lo + ti * TILE;
#pragma unroll
        for (int e = t; e < TILE * 8; e += 256) {
            int sloc = e >> 3, q = e & 7;
            int s = s0 + sloc;
            float* dstp = Ys + b * YS_BUF + sloc * YS_STRIDE + q * 4;
            if (s < s_hi)
                cp16(smem_u32(dstp), y + ((size_t)s * IN_F + i0) * OUT_F + q * 4);
            else
                *(float4*)dstp = make_float4(0.f, 0.f, 0.f, 0.f);
        }
    };

    // prolog: basis tile 0 (direct), prefetch tile 1 into registers
    {
        int s = s_lo + t;
        bool v = s < s_hi;
        float a0 = v ? __ldg(xT0 + s) : 0.f;
        float a1 = v ? __ldg(xT1 + s) : 0.f;
        stage_basis_reg(0, a0, a1, v);
    }
    float pf0 = 0.f, pf1 = 0.f;
    bool pfv = false;
    if (nt > 1) {
        int s = s_lo + TILE + t;
        pfv = s < s_hi;
        if (pfv) { pf0 = __ldg(xT0 + s); pf1 = __ldg(xT1 + s); }
    }
    issue_y(0); cp_commit();
    if (nt > 1) issue_y(1);
    cp_commit();
    if (nt > 2) issue_y(2);
    cp_commit();

    for (int i = 0; i < nt; i++) {
        const int b = i % YS_NBUF, b2 = i & 1;
        cp_wait2();
        __syncthreads();
        if (i + 3 < nt) issue_y(i + 3);
        cp_commit();

        const float* BsC = Bs + b2 * BS_BUF + fw * BS_FEAT;
        const float* YsC = Ys + b * YS_BUF;
#pragma unroll
        for (int jj = 0; jj < 4; jj++) {
            int sl = sh * 128 + jj * 32 + lane;
            const float* brow = BsC + sl * BS_STRIDE;
            const float4* yrow = (const float4*)(YsC + sl * YS_STRIDE + fw * 16 + oh * 8);
            float4 ya = yrow[0];
            float4 yb = yrow[1];
            ull b2v[6];
#pragma unroll
            for (int kp = 0; kp < 6; kp++)
                b2v[kp] = *(const ull*)(brow + 2 * kp);
            ull yB[8];
            yB[0] = bcast2(ya.x); yB[1] = bcast2(ya.y);
            yB[2] = bcast2(ya.z); yB[3] = bcast2(ya.w);
            yB[4] = bcast2(yb.x); yB[5] = bcast2(yb.y);
            yB[6] = bcast2(yb.z); yB[7] = bcast2(yb.w);
#pragma unroll
            for (int kp = 0; kp < 6; kp++)
#pragma unroll
                for (int o = 0; o < 8; o++)
                    fma2(acc[kp * 8 + o], b2v[kp], yB[o]);
        }

        // stage basis for tile i+1 from prefetched registers
        if (i + 1 < nt) stage_basis_reg((i + 1) & 1, pf0, pf1, pfv);
        // prefetch xT for tile i+2 (latency hidden by next iteration's FMA block)
        if (i + 2 < nt) {
            int s = s_lo + (i + 2) * TILE + t;
            pfv = s < s_hi;
            pf0 = pfv ? __ldg(xT0 + s) : 0.f;
            pf1 = pfv ? __ldg(xT1 + s) : 0.f;
        } else {
            pfv = false;
        }
    }

#pragma unroll
    for (int q = 0; q < 48; q++) acc[q] = wred2(acc[q]);
    if (lane == 0) {
        size_t base = ((((size_t)(i0 + fw) * NCH + chunk) * 2 + sh) * 2 + oh) * 96;
#pragma unroll
        for (int o = 0; o < 8; o++)
#pragma unroll
            for (int kp = 0; kp < 6; kp++)
                *(ull*)(g_pAtB + base + o * 12 + 2 * kp) = acc[kp * 8 + o];
    }
}

// triangle index (a <= b)
__device__ __forceinline__ int tidx(int a, int b) {
    return a * KB - (a * (a - 1)) / 2 + (b - a);
}

__device__ __constant__ double CAD[4][4] = {
    {1.0, -3.0,  3.0, -1.0},
    {4.0,  0.0, -6.0,  3.0},
    {1.0,  3.0,  3.0, -3.0},
    {0.0,  0.0,  0.0,  1.0}
};

// ---- phase 2: parallel partial reduction + float Cholesky solve ------------
__global__ __launch_bounds__(256) void solve_kernel(float* __restrict__ out) {
    const int i = blockIdx.x;
    const int t = threadIdx.x;      // 256
    __shared__ float  sAtB[12][OUT_F];
    __shared__ double sS[56];
    __shared__ double sAtAd[66];
    __shared__ float  sL[66];
    __shared__ float  sLinv[KB];

    if (t < 192) {
        // one (k,o) per thread; FULL unroll -> front-batched loads, MLP ~55
        int k = t % 12, o = t / 12;
        int ohh = o >> 3, oo = o & 7;
        const float* p = g_pAtB + (size_t)i * (NCH * 2 * 2 * 96)
                       + ohh * 96 + oo * 12 + k;
        float s = 0.f;
#pragma unroll
        for (int cs = 0; cs < NCH * 2; cs++)
            s += p[(size_t)cs * 192];
        sAtB[k][o] = s;
    } else if (t < 248) {
        int p = t - 192;            // 0..55
        const float* q = g_pMom + (size_t)i * (MCH * 56) + p;
        double s = 0.0;
#pragma unroll
        for (int c = 0; c < MCH; c++)
            s += (double)q[c * 56];
        sS[p] = s;
    }
    __syncthreads();

    if (t < 66) {
        int p = t, r = 0;
        while (p >= KB - r) { p -= KB - r; r++; }
        int cc = r + p;
        // 4 independent accumulators for DFMA ILP
        double v0 = 0.0, v1 = 0.0, v2 = 0.0, v3 = 0.0;
        for (int j = 0; j < 8; j++) {
            int a = r - j, b = cc - j;
            if (a >= 0 && a < 4 && b >= 0 && b < 4) {
#pragma unroll
                for (int q1 = 0; q1 < 4; q1++) {
                    double cb = CAD[b][q1];
                    v0 += CAD[a][0] * cb * sS[j * 7 + 0 + q1];
                    v1 += CAD[a][1] * cb * sS[j * 7 + 1 + q1];
                    v2 += CAD[a][2] * cb * sS[j * 7 + 2 + q1];
                    v3 += CAD[a][3] * cb * sS[j * 7 + 3 + q1];
                }
            }
        }
        sAtAd[t] = ((v0 + v1) + (v2 + v3)) / 36.0;
    }
    __syncthreads();

    if (t == 0) {
        for (int j = 0; j < KB; j++) {
            float d = (float)sAtAd[tidx(j, j)];
            for (int m = 0; m < j; m++) { float v = sL[tidx(m, j)]; d -= v * v; }
            d = sqrtf(d);
            sL[tidx(j, j)] = d;
            float inv = 1.0f / d;
            sLinv[j] = inv;
            for (int r = j + 1; r < KB; r++) {
                float s = (float)sAtAd[tidx(j, r)];
                for (int m = 0; m < j; m++) s -= sL[tidx(m, r)] * sL[tidx(m, j)];
                sL[tidx(j, r)] = s * inv;
            }
        }
    }
    __syncthreads();

    if (t < OUT_F) {
        const int o = t;
        float z[KB], X[KB];
#pragma unroll
        for (int r = 0; r < KB; r++) {
            float s = sAtB[r][o];
#pragma unroll
            for (int m = 0; m < KB; m++) if (m < r) s -= sL[tidx(m, r)] * z[m];
            z[r] = s * sLinv[r];
        }
#pragma unroll
        for (int r = KB - 1; r >= 0; r--) {
            float s = z[r];
#pragma unroll
            for (int m = KB - 1; m >= 0; m--) if (m > r) s -= sL[tidx(r, m)] * X[m];
            X[r] = s * sLinv[r];
            out[(size_t)o * (IN_F * KB) + i * KB + r] = X[r];
        }
    }
}

extern "C" void kernel_launch(void* const* d_in, const int* in_sizes, int n_in,
                              void* d_out, int out_size) {
    const float* x = (const float*)d_in[0];
    const float* y = (const float*)d_in[1];
    (void)n_in; (void)out_size;
    float* out = (float*)d_out;
    int N = in_sizes[0] / IN_F;

    cudaFuncSetAttribute(accum_kernel,
                         cudaFuncAttributeMaxDynamicSharedMemorySize,
                         SMEM_FLOATS * (int)sizeof(float));

    dim3 tgrid((N + 31) / 32, IN_F / 32);
    transpose_kernel<<<tgrid, dim3(32, 8)>>>(x, N);

    moments_kernel<<<dim3(MCH, IN_F), 256>>>(N);

    accum_kernel<<<dim3(NCH, 32), 256, SMEM_FLOATS * (int)sizeof(float)>>>(y, N);

    solve_kernel<<<IN_F, 256>>>(out);
}